// round 2
// baseline (speedup 1.0000x reference)
#include <cuda_runtime.h>
#include <math.h>

#define BATCH 8
#define SEQ   2048
#define CDIM  1024
#define HS    64
#define M_TOTAL (BATCH * SEQ)   // 16384

// Scratch for Q, K, V projections (4 MB each). Device globals: allowed.
__device__ float g_q[M_TOTAL * HS];
__device__ float g_k[M_TOTAL * HS];
__device__ float g_v[M_TOTAL * HS];

// ---------------------------------------------------------------------------
// Kernel 1: QKV projection.  [M_TOTAL, CDIM] x [CDIM, HS] -> [M_TOTAL, HS]
// grid = (M_TOTAL/128, 3), block = 256.  blockIdx.y selects Q/K/V.
// 128x64 output tile, BK=16, each thread computes 8x4.
// ---------------------------------------------------------------------------
#define QKV_BM 128
#define QKV_BK 16

__global__ __launch_bounds__(256) void qkv_kernel(
    const float* __restrict__ xq, const float* __restrict__ xkv,
    const float* __restrict__ Wq, const float* __restrict__ Wk,
    const float* __restrict__ Wv)
{
    const int which = blockIdx.y;                 // 0=Q, 1=K, 2=V
    const float* __restrict__ X = (which == 0) ? xq : xkv;
    const float* __restrict__ W = (which == 0) ? Wq : (which == 1 ? Wk : Wv);
    float* __restrict__ O = (which == 0) ? g_q : (which == 1 ? g_k : g_v);

    __shared__ float As[QKV_BK][QKV_BM];   // A tile, transposed: As[k][m]
    __shared__ float Bs[QKV_BK][HS];       // B tile: Bs[k][n]

    const int tid  = threadIdx.x;
    const int trow = tid >> 4;             // 0..15 -> rows trow*8 .. +7
    const int tcol = tid & 15;             // 0..15 -> cols tcol*4 .. +3
    const int m0   = blockIdx.x * QKV_BM;

    float acc[8][4];
#pragma unroll
    for (int r = 0; r < 8; r++)
#pragma unroll
        for (int c = 0; c < 4; c++) acc[r][c] = 0.f;

    for (int k0 = 0; k0 < CDIM; k0 += QKV_BK) {
        // Load A tile: 128 rows x 16 cols = 512 float4; 2 per thread.
#pragma unroll
        for (int i = 0; i < 2; i++) {
            int idx = tid + i * 256;       // 0..511
            int r   = idx >> 2;            // row in tile
            int c4  = (idx & 3) * 4;       // col group
            const float4 v = *(const float4*)&X[(size_t)(m0 + r) * CDIM + k0 + c4];
            As[c4 + 0][r] = v.x;
            As[c4 + 1][r] = v.y;
            As[c4 + 2][r] = v.z;
            As[c4 + 3][r] = v.w;
        }
        // Load B tile: 16 x 64 = 256 float4; 1 per thread.
        {
            int r  = tid >> 4;
            int c4 = (tid & 15) * 4;
            *(float4*)&Bs[r][c4] = *(const float4*)&W[(size_t)(k0 + r) * HS + c4];
        }
        __syncthreads();

#pragma unroll
        for (int k = 0; k < QKV_BK; k++) {
            float a[8], b[4];
            float4 a0 = *(const float4*)&As[k][trow * 8];
            float4 a1 = *(const float4*)&As[k][trow * 8 + 4];
            a[0] = a0.x; a[1] = a0.y; a[2] = a0.z; a[3] = a0.w;
            a[4] = a1.x; a[5] = a1.y; a[6] = a1.z; a[7] = a1.w;
            float4 b0 = *(const float4*)&Bs[k][tcol * 4];
            b[0] = b0.x; b[1] = b0.y; b[2] = b0.z; b[3] = b0.w;
#pragma unroll
            for (int r = 0; r < 8; r++)
#pragma unroll
                for (int c = 0; c < 4; c++)
                    acc[r][c] = fmaf(a[r], b[c], acc[r][c]);
        }
        __syncthreads();
    }

#pragma unroll
    for (int r = 0; r < 8; r++) {
        float4 res = make_float4(acc[r][0], acc[r][1], acc[r][2], acc[r][3]);
        *(float4*)&O[(size_t)(m0 + trow * 8 + r) * HS + tcol * 4] = res;
    }
}

// ---------------------------------------------------------------------------
// Kernel 2: causal flash attention.
// grid = (SEQ/64, BATCH), block = 256. One 64-row Q tile per block.
// Online softmax; thread (ty,tx) owns a 4x4 patch of the 64x64 tiles.
// smem: Qs + KVs (K transposed, then V) + Ps = exactly 48 KB.
// ---------------------------------------------------------------------------
__global__ __launch_bounds__(256) void attn_kernel(float* __restrict__ out)
{
    __shared__ float Qs[64][64];    // Qs[i][h]
    __shared__ float KVs[64][64];   // first K^T: KVs[h][j]; then V: KVs[k][j]
    __shared__ float Ps[64][64];    // P[i][j]

    const int qt  = blockIdx.x;            // 0..31
    const int bb  = blockIdx.y;            // 0..7
    const int tid = threadIdx.x;
    const int tx  = tid & 15;
    const int ty  = tid >> 4;
    const int i0  = ty * 4;
    const int j0  = tx * 4;

    const float scale = 0.03125f;          // 1024^-0.5

    // Load Q tile (4096 floats, 4 float4 per thread).
    const float* Qg = g_q + ((size_t)bb * SEQ + qt * 64) * HS;
#pragma unroll
    for (int i = 0; i < 4; i++) {
        int idx = tid + i * 256;           // 0..1023
        int r   = idx >> 4;
        int c4  = (idx & 15) * 4;
        *(float4*)&Qs[r][c4] = *(const float4*)&Qg[r * HS + c4];
    }

    float o[4][4];
    float m_run[4], l_run[4];
#pragma unroll
    for (int r = 0; r < 4; r++) {
        m_run[r] = -INFINITY;
        l_run[r] = 0.f;
#pragma unroll
        for (int c = 0; c < 4; c++) o[r][c] = 0.f;
    }

    for (int kt = 0; kt <= qt; kt++) {
        const float* Kg = g_k + ((size_t)bb * SEQ + kt * 64) * HS;
        const float* Vg = g_v + ((size_t)bb * SEQ + kt * 64) * HS;

        // Load K tile transposed: KVs[h][j].
#pragma unroll
        for (int i = 0; i < 4; i++) {
            int idx = tid + i * 256;
            int r   = idx >> 4;            // key row j
            int c4  = (idx & 15) * 4;      // h group
            float4 v = *(const float4*)&Kg[r * HS + c4];
            KVs[c4 + 0][r] = v.x;
            KVs[c4 + 1][r] = v.y;
            KVs[c4 + 2][r] = v.z;
            KVs[c4 + 3][r] = v.w;
        }
        __syncthreads();   // K^T ready (also covers initial Qs on first iter)

        // S = (Q K^T) * scale, causal mask on diagonal tile.
        float s[4][4];
#pragma unroll
        for (int r = 0; r < 4; r++)
#pragma unroll
            for (int c = 0; c < 4; c++) s[r][c] = 0.f;

        for (int h = 0; h < 64; h++) {
            float4 bv = *(const float4*)&KVs[h][j0];
            float a0 = Qs[i0 + 0][h];
            float a1 = Qs[i0 + 1][h];
            float a2 = Qs[i0 + 2][h];
            float a3 = Qs[i0 + 3][h];
            s[0][0] = fmaf(a0, bv.x, s[0][0]); s[0][1] = fmaf(a0, bv.y, s[0][1]);
            s[0][2] = fmaf(a0, bv.z, s[0][2]); s[0][3] = fmaf(a0, bv.w, s[0][3]);
            s[1][0] = fmaf(a1, bv.x, s[1][0]); s[1][1] = fmaf(a1, bv.y, s[1][1]);
            s[1][2] = fmaf(a1, bv.z, s[1][2]); s[1][3] = fmaf(a1, bv.w, s[1][3]);
            s[2][0] = fmaf(a2, bv.x, s[2][0]); s[2][1] = fmaf(a2, bv.y, s[2][1]);
            s[2][2] = fmaf(a2, bv.z, s[2][2]); s[2][3] = fmaf(a2, bv.w, s[2][3]);
            s[3][0] = fmaf(a3, bv.x, s[3][0]); s[3][1] = fmaf(a3, bv.y, s[3][1]);
            s[3][2] = fmaf(a3, bv.z, s[3][2]); s[3][3] = fmaf(a3, bv.w, s[3][3]);
        }

        const bool diag = (kt == qt);
#pragma unroll
        for (int r = 0; r < 4; r++)
#pragma unroll
            for (int c = 0; c < 4; c++) {
                float sv = s[r][c] * scale;
                if (diag && (j0 + c) > (i0 + r)) sv = -INFINITY;
                s[r][c] = sv;
            }

        // Row max (local 4 + shuffle across 16-lane group).
        float rmax[4];
#pragma unroll
        for (int r = 0; r < 4; r++) {
            float mx = fmaxf(fmaxf(s[r][0], s[r][1]), fmaxf(s[r][2], s[r][3]));
            rmax[r] = mx;
        }
#pragma unroll
        for (int off = 8; off > 0; off >>= 1)
#pragma unroll
            for (int r = 0; r < 4; r++)
                rmax[r] = fmaxf(rmax[r], __shfl_xor_sync(0xffffffffu, rmax[r], off));

        float alpha[4];
#pragma unroll
        for (int r = 0; r < 4; r++) {
            float mn = fmaxf(m_run[r], rmax[r]);
            alpha[r] = __expf(m_run[r] - mn);   // -inf-finite -> 0 on first iter
            m_run[r] = mn;
        }

        float rsum[4] = {0.f, 0.f, 0.f, 0.f};
#pragma unroll
        for (int r = 0; r < 4; r++)
#pragma unroll
            for (int c = 0; c < 4; c++) {
                float p = __expf(s[r][c] - m_run[r]);   // exp(-inf)=0 for masked
                Ps[i0 + r][j0 + c] = p;
                rsum[r] += p;
            }
#pragma unroll
        for (int off = 8; off > 0; off >>= 1)
#pragma unroll
            for (int r = 0; r < 4; r++)
                rsum[r] += __shfl_xor_sync(0xffffffffu, rsum[r], off);

#pragma unroll
        for (int r = 0; r < 4; r++) {
            l_run[r] = l_run[r] * alpha[r] + rsum[r];
#pragma unroll
            for (int c = 0; c < 4; c++) o[r][c] *= alpha[r];
        }

        __syncthreads();   // all reads of K^T and writes of Ps done

        // Load V tile (natural layout): KVs[k][j].
#pragma unroll
        for (int i = 0; i < 4; i++) {
            int idx = tid + i * 256;
            int r   = idx >> 4;
            int c4  = (idx & 15) * 4;
            *(float4*)&KVs[r][c4] = *(const float4*)&Vg[r * HS + c4];
        }
        __syncthreads();   // V + Ps ready

        // O += P V
        for (int k = 0; k < 64; k++) {
            float4 bv = *(const float4*)&KVs[k][j0];
            float p0 = Ps[i0 + 0][k];
            float p1 = Ps[i0 + 1][k];
            float p2 = Ps[i0 + 2][k];
            float p3 = Ps[i0 + 3][k];
            o[0][0] = fmaf(p0, bv.x, o[0][0]); o[0][1] = fmaf(p0, bv.y, o[0][1]);
            o[0][2] = fmaf(p0, bv.z, o[0][2]); o[0][3] = fmaf(p0, bv.w, o[0][3]);
            o[1][0] = fmaf(p1, bv.x, o[1][0]); o[1][1] = fmaf(p1, bv.y, o[1][1]);
            o[1][2] = fmaf(p1, bv.z, o[1][2]); o[1][3] = fmaf(p1, bv.w, o[1][3]);
            o[2][0] = fmaf(p2, bv.x, o[2][0]); o[2][1] = fmaf(p2, bv.y, o[2][1]);
            o[2][2] = fmaf(p2, bv.z, o[2][2]); o[2][3] = fmaf(p2, bv.w, o[2][3]);
            o[3][0] = fmaf(p3, bv.x, o[3][0]); o[3][1] = fmaf(p3, bv.y, o[3][1]);
            o[3][2] = fmaf(p3, bv.z, o[3][2]); o[3][3] = fmaf(p3, bv.w, o[3][3]);
        }
        __syncthreads();   // before next iter overwrites KVs / Ps
    }

    // Final normalize + store.
#pragma unroll
    for (int r = 0; r < 4; r++) {
        float inv = 1.f / l_run[r];
        float4 res = make_float4(o[r][0] * inv, o[r][1] * inv,
                                 o[r][2] * inv, o[r][3] * inv);
        *(float4*)&out[((size_t)bb * SEQ + qt * 64 + i0 + r) * HS + j0] = res;
    }
}

// ---------------------------------------------------------------------------
extern "C" void kernel_launch(void* const* d_in, const int* in_sizes, int n_in,
                              void* d_out, int out_size)
{
    const float* xq  = (const float*)d_in[0];
    const float* xkv = (const float*)d_in[1];
    const float* Wq  = (const float*)d_in[2];
    const float* Wk  = (const float*)d_in[3];
    const float* Wv  = (const float*)d_in[4];
    float* out = (float*)d_out;

    qkv_kernel<<<dim3(M_TOTAL / QKV_BM, 3), 256>>>(xq, xkv, Wq, Wk, Wv);
    attn_kernel<<<dim3(SEQ / 64, BATCH), 256>>>(out);
}